// round 1
// baseline (speedup 1.0000x reference)
#include <cuda_runtime.h>

#define MAXR 100.0f

// Scratch for per-pixel alpha/beta (device globals: allocation-free).
__device__ float g_alpha[16384];
__device__ float g_beta[16384];

__device__ __forceinline__ float tanh_fast(float x) {
    float r;
    asm("tanh.approx.f32 %0, %1;" : "=f"(r) : "f"(x));
    return r;
}

// ---------------------------------------------------------------------------
// Kernel 1: 3x3 conv (C=64 -> 2 outputs), SAME padding, then 100*tanh(.+bias).
// One thread per pixel; weights staged in shared memory.
// ---------------------------------------------------------------------------
__global__ void conv_ab_kernel(const float* __restrict__ x,
                               const float* __restrict__ w,
                               const float* __restrict__ bias) {
    __shared__ float sw[1152];  // [2][64][3][3]
    for (int i = threadIdx.x; i < 1152; i += blockDim.x) sw[i] = w[i];
    __syncthreads();

    int p  = blockIdx.x * blockDim.x + threadIdx.x;  // 0..16383
    int b  = p >> 12;
    int hw = p & 4095;
    int h  = hw >> 6;
    int wd = hw & 63;
    const float* xb = x + b * 262144;

    float a0 = bias[0];
    float a1 = bias[1];

    #pragma unroll 4
    for (int c = 0; c < 64; c++) {
        const float* xc = xb + c * 4096;
        const float* w0 = sw + c * 9;
        const float* w1 = sw + 576 + c * 9;
        #pragma unroll
        for (int kh = 0; kh < 3; kh++) {
            int hh = h + kh - 1;
            if ((unsigned)hh >= 64u) continue;
            #pragma unroll
            for (int kw = 0; kw < 3; kw++) {
                int ww = wd + kw - 1;
                if ((unsigned)ww >= 64u) continue;
                float v = xc[hh * 64 + ww];
                a0 = fmaf(v, w0[kh * 3 + kw], a0);
                a1 = fmaf(v, w1[kh * 3 + kw], a1);
            }
        }
    }
    g_alpha[p] = MAXR * tanhf(a0);
    g_beta[p]  = MAXR * tanhf(a1);
}

// ---------------------------------------------------------------------------
// Kernel 2: per-pixel C x C interaction + softmax-weighted channel sum.
// One warp per pixel; 8 pixels per block. Channel vectors staged in smem
// (coalesced load), inner loop is 2 MUFU.TANH per (i, lane).
// ---------------------------------------------------------------------------
__global__ __launch_bounds__(256) void dsf_main_kernel(
    const float* __restrict__ x, float* __restrict__ out) {
    __shared__ float sx[8][64];

    int tid = threadIdx.x;
    int p0  = blockIdx.x * 8;
    int b   = p0 >> 12;
    int hw0 = p0 & 4095;
    const float* xb = x + b * 262144 + hw0;

    // Coalesced cooperative load: 8 pixels x 64 channels = 512 floats.
    for (int e = tid; e < 512; e += 256) {
        int c = e >> 3;
        int q = e & 7;
        sx[q][c] = xb[c * 4096 + q];
    }
    __syncthreads();

    int wid  = tid >> 5;
    int lane = tid & 31;
    int p    = p0 + wid;

    float alpha = g_alpha[p];
    float beta  = g_beta[p];

    const float* v = sx[wid];
    float xj0 = v[lane];
    float xj1 = v[lane + 32];
    float acc0 = 0.0f, acc1 = 0.0f;

    #pragma unroll
    for (int i = 0; i < 64; i++) {
        float yi = beta * v[i];          // LDS broadcast
        float d0 = yi - xj0;
        float d1 = yi - xj1;
        acc0 = fmaf(d0, tanh_fast(alpha * d0), acc0);
        acc1 = fmaf(d1, tanh_fast(alpha * d1), acc1);
    }

    // logits = clip(-alpha * mean_i(...), +-100)
    float l0 = fminf(fmaxf(-alpha * (acc0 * (1.0f / 64.0f)), -MAXR), MAXR);
    float l1 = fminf(fmaxf(-alpha * (acc1 * (1.0f / 64.0f)), -MAXR), MAXR);

    // warp softmax over 64 logits (2 per lane)
    float m = fmaxf(l0, l1);
    #pragma unroll
    for (int o = 16; o > 0; o >>= 1)
        m = fmaxf(m, __shfl_xor_sync(0xffffffffu, m, o));

    float e0 = __expf(l0 - m);
    float e1 = __expf(l1 - m);
    float num = fmaf(xj0, e0, xj1 * e1);
    float den = e0 + e1;
    #pragma unroll
    for (int o = 16; o > 0; o >>= 1) {
        num += __shfl_xor_sync(0xffffffffu, num, o);
        den += __shfl_xor_sync(0xffffffffu, den, o);
    }

    if (lane == 0) out[p] = num / den;
}

extern "C" void kernel_launch(void* const* d_in, const int* in_sizes, int n_in,
                              void* d_out, int out_size) {
    const float* x    = (const float*)d_in[0];
    const float* w    = (const float*)d_in[1];
    const float* bias = (const float*)d_in[2];
    float* out        = (float*)d_out;

    conv_ab_kernel<<<128, 128>>>(x, w, bias);
    dsf_main_kernel<<<2048, 256>>>(x, out);
}

// round 2
// speedup vs baseline: 2.0036x; 2.0036x over previous
#include <cuda_runtime.h>

#define MAXR 100.0f

__device__ __forceinline__ float tanh_fast(float x) {
    float r;
    asm("tanh.approx.f32 %0, %1;" : "=f"(r) : "f"(x));
    return r;
}

// ---------------------------------------------------------------------------
// Fused kernel: per block = 8 consecutive same-row pixels (b, h, w0..w0+7).
// Phase 1: load 64ch x 3row x 10col halo tile + conv weights into smem.
// Phase 2: each warp computes its pixel's 3x3 conv -> alpha, beta.
// Phase 3: per-pixel C x C tanh interaction + softmax-weighted channel sum,
//          reading channel vectors from the tile's center column.
// ---------------------------------------------------------------------------
__global__ __launch_bounds__(256) void dsf_fused_kernel(
    const float* __restrict__ x,
    const float* __restrict__ wgt,
    const float* __restrict__ bias,
    float* __restrict__ out) {

    __shared__ float tile[64][31];  // [c][r*10+cc], stride 31 => conflict-free
    __shared__ float sw[1152];      // [o=2][c=64][3][3]

    int tid = threadIdx.x;
    int p0  = blockIdx.x * 8;
    int b   = p0 >> 12;
    int hw0 = p0 & 4095;
    int h   = hw0 >> 6;
    int w0  = hw0 & 63;             // multiple of 8
    const float* xb = x + b * 262144;

    // ---- Phase 1: cooperative tile + weight load --------------------------
    for (int e = tid; e < 1920; e += 256) {
        int c   = e / 30;
        int rem = e - c * 30;
        int r   = rem / 10;
        int cc  = rem - r * 10;
        int hh  = h + r - 1;
        int ww  = w0 + cc - 1;
        float v = 0.0f;
        if ((unsigned)hh < 64u && (unsigned)ww < 64u)
            v = xb[c * 4096 + hh * 64 + ww];
        tile[c][r * 10 + cc] = v;
    }
    for (int e = tid; e < 1152; e += 256) sw[e] = wgt[e];
    __syncthreads();

    int wid  = tid >> 5;   // pixel within block (0..7)
    int lane = tid & 31;

    // ---- Phase 2: 3x3 conv for this warp's pixel --------------------------
    // Each lane handles channels {lane, lane+32}.
    float a0 = 0.0f, a1 = 0.0f;
    #pragma unroll
    for (int g = 0; g < 2; g++) {
        int c = lane + g * 32;
        const float* t  = &tile[c][0];
        const float* W0 = &sw[c * 9];
        const float* W1 = &sw[576 + c * 9];
        #pragma unroll
        for (int r = 0; r < 3; r++) {
            #pragma unroll
            for (int cc = 0; cc < 3; cc++) {
                float v = t[r * 10 + wid + cc];
                a0 = fmaf(v, W0[r * 3 + cc], a0);
                a1 = fmaf(v, W1[r * 3 + cc], a1);
            }
        }
    }
    #pragma unroll
    for (int o = 16; o > 0; o >>= 1) {
        a0 += __shfl_xor_sync(0xffffffffu, a0, o);
        a1 += __shfl_xor_sync(0xffffffffu, a1, o);
    }
    // Accurate tanh here: alpha/beta errors are amplified 100x downstream.
    float alpha = MAXR * tanhf(a0 + __ldg(&bias[0]));
    float beta  = MAXR * tanhf(a1 + __ldg(&bias[1]));

    // ---- Phase 3: C x C interaction + softmax -----------------------------
    // Channel vector of this pixel = tile[:][11 + wid] (center row, center col)
    const int ctr = 11 + wid;       // r=1 -> offset 10, +1 halo, +wid
    float xj0 = tile[lane][ctr];
    float xj1 = tile[lane + 32][ctr];
    float acc0 = 0.0f, acc1 = 0.0f;

    #pragma unroll
    for (int i = 0; i < 64; i++) {
        float yi = beta * tile[i][ctr];   // LDS broadcast
        float d0 = yi - xj0;
        float d1 = yi - xj1;
        acc0 = fmaf(d0, tanh_fast(alpha * d0), acc0);
        acc1 = fmaf(d1, tanh_fast(alpha * d1), acc1);
    }

    float l0 = fminf(fmaxf(-alpha * (acc0 * (1.0f / 64.0f)), -MAXR), MAXR);
    float l1 = fminf(fmaxf(-alpha * (acc1 * (1.0f / 64.0f)), -MAXR), MAXR);

    float m = fmaxf(l0, l1);
    #pragma unroll
    for (int o = 16; o > 0; o >>= 1)
        m = fmaxf(m, __shfl_xor_sync(0xffffffffu, m, o));

    float e0 = __expf(l0 - m);
    float e1 = __expf(l1 - m);
    float num = fmaf(xj0, e0, xj1 * e1);
    float den = e0 + e1;
    #pragma unroll
    for (int o = 16; o > 0; o >>= 1) {
        num += __shfl_xor_sync(0xffffffffu, num, o);
        den += __shfl_xor_sync(0xffffffffu, den, o);
    }

    if (lane == 0) out[p0 + wid] = num / den;
}

extern "C" void kernel_launch(void* const* d_in, const int* in_sizes, int n_in,
                              void* d_out, int out_size) {
    const float* x    = (const float*)d_in[0];
    const float* w    = (const float*)d_in[1];
    const float* bias = (const float*)d_in[2];
    float* out        = (float*)d_out;

    dsf_fused_kernel<<<2048, 256>>>(x, w, bias, out);
}

// round 3
// speedup vs baseline: 2.1225x; 1.0593x over previous
#include <cuda_runtime.h>

#define MAXR 100.0f

__device__ __forceinline__ float tanh_fast(float x) {
    float r;
    asm("tanh.approx.f32 %0, %1;" : "=f"(r) : "f"(x));
    return r;
}

// ---------------------------------------------------------------------------
// Fused kernel: per block = 8 consecutive same-row pixels (b, h, w0..w0+7).
// Phase 1: load 64ch x 3row x 10col halo tile + conv weights into smem.
// Phase 2: each warp computes its pixel's 3x3 conv -> alpha, beta.
// Phase 3: z_ij = u_i + nc_j with u_i = (alpha*beta)*x_i precomputed in smem,
//          nc_j = -alpha*x_j in registers. logit_j = -(1/64) sum_i z*tanh(z)
//          (the alpha factors cancel exactly). Softmax-weighted channel sum.
// ---------------------------------------------------------------------------
__global__ __launch_bounds__(256) void dsf_fused_kernel(
    const float* __restrict__ x,
    const float* __restrict__ wgt,
    const float* __restrict__ bias,
    float* __restrict__ out) {

    __shared__ float tile[64][31];  // [c][r*10+cc], stride 31 => conflict-free
    __shared__ float sw[1152];      // [o=2][c=64][3][3]
    __shared__ float su[8][64];     // per-pixel u_i = alpha*beta*x_i

    int tid = threadIdx.x;
    int p0  = blockIdx.x * 8;
    int b   = p0 >> 12;
    int hw0 = p0 & 4095;
    int h   = hw0 >> 6;
    int w0  = hw0 & 63;             // multiple of 8
    const float* xb = x + b * 262144;

    // ---- Phase 1: cooperative tile + weight load --------------------------
    for (int e = tid; e < 1920; e += 256) {
        int c   = e / 30;
        int rem = e - c * 30;
        int r   = rem / 10;
        int cc  = rem - r * 10;
        int hh  = h + r - 1;
        int ww  = w0 + cc - 1;
        float v = 0.0f;
        if ((unsigned)hh < 64u && (unsigned)ww < 64u)
            v = xb[c * 4096 + hh * 64 + ww];
        tile[c][r * 10 + cc] = v;
    }
    for (int e = tid; e < 1152; e += 256) sw[e] = wgt[e];
    __syncthreads();

    int wid  = tid >> 5;   // pixel within block (0..7)
    int lane = tid & 31;

    // ---- Phase 2: 3x3 conv for this warp's pixel --------------------------
    float a0 = 0.0f, a1 = 0.0f;
    #pragma unroll
    for (int g = 0; g < 2; g++) {
        int c = lane + g * 32;
        const float* t  = &tile[c][0];
        const float* W0 = &sw[c * 9];
        const float* W1 = &sw[576 + c * 9];
        #pragma unroll
        for (int r = 0; r < 3; r++) {
            #pragma unroll
            for (int cc = 0; cc < 3; cc++) {
                float v = t[r * 10 + wid + cc];
                a0 = fmaf(v, W0[r * 3 + cc], a0);
                a1 = fmaf(v, W1[r * 3 + cc], a1);
            }
        }
    }
    #pragma unroll
    for (int o = 16; o > 0; o >>= 1) {
        a0 += __shfl_xor_sync(0xffffffffu, a0, o);
        a1 += __shfl_xor_sync(0xffffffffu, a1, o);
    }
    // Accurate tanh here: alpha/beta errors are amplified 100x downstream.
    float alpha = MAXR * tanhf(a0 + __ldg(&bias[0]));
    float beta  = MAXR * tanhf(a1 + __ldg(&bias[1]));

    // ---- Phase 3 setup: u_i = (alpha*beta)*x_i into smem ------------------
    const int ctr = 11 + wid;       // center element: r=1 (offset 10) + halo 1 + wid
    float xj0 = tile[lane][ctr];
    float xj1 = tile[lane + 32][ctr];

    float ab = alpha * beta;
    su[wid][lane]      = ab * xj0;
    su[wid][lane + 32] = ab * xj1;
    __syncwarp();

    float nc0 = -alpha * xj0;
    float nc1 = -alpha * xj1;
    float acc0 = 0.0f, acc1 = 0.0f;
    const float* uu = su[wid];

    // ---- Main C x C loop: 6 instructions per iteration --------------------
    #pragma unroll
    for (int i = 0; i < 64; i++) {
        float u  = uu[i];           // LDS broadcast
        float z0 = u + nc0;
        float z1 = u + nc1;
        acc0 = fmaf(z0, tanh_fast(z0), acc0);
        acc1 = fmaf(z1, tanh_fast(z1), acc1);
    }

    // logit_j = clip(-(1/64) * sum_i z*tanh(z), +-100)  (alpha cancels)
    float l0 = fminf(fmaxf(acc0 * (-1.0f / 64.0f), -MAXR), MAXR);
    float l1 = fminf(fmaxf(acc1 * (-1.0f / 64.0f), -MAXR), MAXR);

    // warp softmax over 64 logits (2 per lane)
    float m = fmaxf(l0, l1);
    #pragma unroll
    for (int o = 16; o > 0; o >>= 1)
        m = fmaxf(m, __shfl_xor_sync(0xffffffffu, m, o));

    float e0 = __expf(l0 - m);
    float e1 = __expf(l1 - m);
    float num = fmaf(xj0, e0, xj1 * e1);
    float den = e0 + e1;
    #pragma unroll
    for (int o = 16; o > 0; o >>= 1) {
        num += __shfl_xor_sync(0xffffffffu, num, o);
        den += __shfl_xor_sync(0xffffffffu, den, o);
    }

    if (lane == 0) out[p0 + wid] = num / den;
}

extern "C" void kernel_launch(void* const* d_in, const int* in_sizes, int n_in,
                              void* d_out, int out_size) {
    const float* x    = (const float*)d_in[0];
    const float* w    = (const float*)d_in[1];
    const float* bias = (const float*)d_in[2];
    float* out        = (float*)d_out;

    dsf_fused_kernel<<<2048, 256>>>(x, w, bias, out);
}